// round 9
// baseline (speedup 1.0000x reference)
#include <cuda_runtime.h>

#define BB 32
#define SS 1024
#define DD 512
#define DD4 (DD/4)
#define MAXL 8192   // durations in [1,8], S=1024 -> mel_len <= 8192

// Scratch (no device allocation allowed)
__device__ __align__(16) int g_csum[BB * SS];   // per-batch inclusive scan
__device__ __align__(16) int g_sum32[BB * 32];  // level-1 summary: csum[b][32j+31]

// ---------------------------------------------------------------------------
// K1: scan + ALL small outputs (mel_len, mask). 32 blocks x 256 threads.
// Triggers the PDL secondary launch as soon as the scan results are stored.
// ---------------------------------------------------------------------------
__global__ __launch_bounds__(256)
void lr_scan_kernel(const int* __restrict__ dur,
                    float* __restrict__ mel_len_out,
                    float* __restrict__ mask_out,
                    int max_len, int has_tail)
{
    __shared__ int wsum[8];
    const int b    = blockIdx.x;
    const int tid  = threadIdx.x;
    const int lane = tid & 31;
    const int wid  = tid >> 5;

    const int4 d = __ldg(((const int4*)(dur + b * SS)) + tid);
    const int p0 = d.x;
    const int p1 = p0 + d.y;
    const int p2 = p1 + d.z;
    const int p3 = p2 + d.w;
    int tot = p3;

    #pragma unroll
    for (int off = 1; off < 32; off <<= 1) {
        int n = __shfl_up_sync(0xffffffff, tot, off);
        if (lane >= off) tot += n;
    }
    if (lane == 31) wsum[wid] = tot;
    __syncthreads();
    if (wid == 0 && lane < 8) {
        int w = wsum[lane];
        #pragma unroll
        for (int off = 1; off < 8; off <<= 1) {
            int n = __shfl_up_sync(0xff, w, off);
            if (lane >= off) w += n;
        }
        wsum[lane] = w;
    }
    __syncthreads();

    const int base = (tot - p3) + ((wid > 0) ? wsum[wid - 1] : 0);
    int4 o;
    o.x = base + p0; o.y = base + p1; o.z = base + p2; o.w = base + p3;
    ((int4*)(g_csum + b * SS))[tid] = o;

    // level-1 summary: element 4*tid+3 == 32j+31  <=>  tid % 8 == 7
    if ((tid & 7) == 7) g_sum32[(b << 5) + (tid >> 3)] = o.w;

    // scan results stored -> let the expand grid start launching
    cudaTriggerProgrammaticLaunchCompletion();

    __syncthreads();
    const int mel = ((volatile int*)g_csum)[b * SS + SS - 1];  // via smem? no: recompute
    // (o.w of tid==255 is the total; broadcast through shared)
    __shared__ int s_mel;
    if (tid == 255) s_mel = o.w;
    __syncthreads();
    const int melv = s_mel;
    (void)mel;

    if (has_tail) {
        if (tid == 0) mel_len_out[b] = (float)melv;
        float* mrow = mask_out + (long)b * max_len;
        for (int t = tid; t < max_len; t += 256)
            mrow[t] = (t >= melv) ? 1.0f : 0.0f;
    }
}

// ---------------------------------------------------------------------------
// K2: streaming expand, ONE WARP PER OUTPUT ROW (PDL secondary).
// Prologue (index math) runs before gridDependencySynchronize; then the
// 2-level 32-ary warp search (2 L1-hot 128B loads + 2 ballots) and the
// 4x LDG.128 + 4x STG.128 streaming payload.
// ---------------------------------------------------------------------------
__global__ __launch_bounds__(256)
void lr_expand_kernel(const float4* __restrict__ x4,
                      float4*       __restrict__ out4,
                      int max_len, int total_rows)
{
    const int row  = (blockIdx.x * blockDim.x + threadIdx.x) >> 5;
    const int lane = threadIdx.x & 31;
    if (row >= total_rows) {
        cudaGridDependencySynchronize();
        return;
    }

    const int b = row / max_len;              // warp-uniform
    const int t = row - b * max_len;
    const long out_base = (long)row * DD4 + lane;

    // wait for K1's scan results to be visible
    cudaGridDependencySynchronize();

    // level 1: 32 segment maxima (one 128B line, L1-hot)
    const int s1  = __ldg(&g_sum32[(b << 5) + lane]);
    const int mel = __shfl_sync(0xffffffff, s1, 31);

    if (t >= mel) {                           // warp-uniform padding path
        const float4 z = make_float4(0.f, 0.f, 0.f, 0.f);
        __stcs(&out4[out_base],      z);
        __stcs(&out4[out_base + 32], z);
        __stcs(&out4[out_base + 64], z);
        __stcs(&out4[out_base + 96], z);
        return;
    }

    const unsigned m1  = __ballot_sync(0xffffffff, s1 > t);
    const int      seg = __ffs(m1) - 1;

    // level 2: 32 entries of the winning segment (one 128B line)
    const int s2 = __ldg(&g_csum[(b << 10) + (seg << 5) + lane]);
    const unsigned m2 = __ballot_sync(0xffffffff, s2 > t);
    const int lo = (seg << 5) + __ffs(m2) - 1;   // first i with csum[i] > t

    const long in_base = ((long)(b * SS + lo)) * DD4 + lane;
    float4 v0 = __ldg(&x4[in_base]);
    float4 v1 = __ldg(&x4[in_base + 32]);
    float4 v2 = __ldg(&x4[in_base + 64]);
    float4 v3 = __ldg(&x4[in_base + 96]);
    __stcs(&out4[out_base],      v0);
    __stcs(&out4[out_base + 32], v1);
    __stcs(&out4[out_base + 64], v2);
    __stcs(&out4[out_base + 96], v3);
}

// ---------------------------------------------------------------------------
extern "C" void kernel_launch(void* const* d_in, const int* in_sizes, int n_in,
                              void* d_out, int out_size)
{
    const float* x   = (const float*)d_in[0];
    const int*   dur = (const int*)d_in[1];
    float*       out = (float*)d_out;

    // Recover max_len from out_size (tuple layout vs expanded-only).
    long L;
    int has_tail;
    long os = (long)out_size;
    if ((os - BB) > 0 && ((os - BB) % ((long)BB * (DD + 1))) == 0) {
        L = (os - BB) / ((long)BB * (DD + 1));
        has_tail = 1;
    } else {
        L = os / ((long)BB * DD);
        has_tail = 0;
    }
    if (L <= 0 || L > MAXL) return;

    const int max_len = (int)L;
    const int total_rows = BB * max_len;

    float* mel_len_out = out + (long)BB * max_len * DD;   // B floats
    float* mask_out    = mel_len_out + BB;                // B*L floats

    // K1: scan + mask/mel_len (primary)
    lr_scan_kernel<<<BB, 256>>>(dur, mel_len_out, mask_out, max_len, has_tail);

    // K2: expand (PDL secondary) — launch overlaps K1's tail
    {
        const int warps_per_block = 256 / 32;
        const int blocks = (total_rows + warps_per_block - 1) / warps_per_block;

        cudaLaunchConfig_t cfg = {};
        cfg.gridDim  = dim3((unsigned)blocks, 1, 1);
        cfg.blockDim = dim3(256, 1, 1);
        cudaLaunchAttribute attr[1];
        attr[0].id = cudaLaunchAttributeProgrammaticStreamSerialization;
        attr[0].val.programmaticStreamSerializationAllowed = 1;
        cfg.attrs = attr;
        cfg.numAttrs = 1;

        cudaLaunchKernelEx(&cfg, lr_expand_kernel,
                           (const float4*)x, (float4*)out, max_len, total_rows);
    }
}

// round 10
// speedup vs baseline: 1.0046x; 1.0046x over previous
#include <cuda_runtime.h>

#define BB 32
#define SS 1024
#define DD 512
#define DD4 (DD/4)
#define MAXL 8192   // durations in [1,8], S=1024 -> mel_len <= 8192

// Scratch (no device allocation allowed)
__device__ __align__(16) int g_csum[BB * SS];   // per-batch inclusive scan
__device__ __align__(16) int g_sum32[BB * 32];  // level-1 summary: csum[b][32j+31]

// 256-bit global load (L1-bypass/nc) and streaming store, sm_100+/PTX v8 vectors
__device__ __forceinline__ void ldg256(const float* p, float* v) {
    asm volatile("ld.global.nc.v8.f32 {%0,%1,%2,%3,%4,%5,%6,%7}, [%8];"
                 : "=f"(v[0]), "=f"(v[1]), "=f"(v[2]), "=f"(v[3]),
                   "=f"(v[4]), "=f"(v[5]), "=f"(v[6]), "=f"(v[7])
                 : "l"(p));
}
__device__ __forceinline__ void stg256_cs(float* p, const float* v) {
    asm volatile("st.global.cs.v8.f32 [%0], {%1,%2,%3,%4,%5,%6,%7,%8};"
                 :: "l"(p),
                    "f"(v[0]), "f"(v[1]), "f"(v[2]), "f"(v[3]),
                    "f"(v[4]), "f"(v[5]), "f"(v[6]), "f"(v[7])
                 : "memory");
}

// ---------------------------------------------------------------------------
// K1: pure scan. 32 blocks x 256 threads, int4 per thread.
// Writes g_csum, the 32-entry per-batch summary, and the mel_len fp32 tail.
// ---------------------------------------------------------------------------
__global__ __launch_bounds__(256)
void lr_scan_kernel(const int* __restrict__ dur,
                    float* __restrict__ mel_len_out,
                    int has_tail)
{
    __shared__ int wsum[8];
    const int b    = blockIdx.x;
    const int tid  = threadIdx.x;
    const int lane = tid & 31;
    const int wid  = tid >> 5;

    const int4 d = __ldg(((const int4*)(dur + b * SS)) + tid);
    const int p0 = d.x;
    const int p1 = p0 + d.y;
    const int p2 = p1 + d.z;
    const int p3 = p2 + d.w;
    int tot = p3;

    #pragma unroll
    for (int off = 1; off < 32; off <<= 1) {
        int n = __shfl_up_sync(0xffffffff, tot, off);
        if (lane >= off) tot += n;
    }
    if (lane == 31) wsum[wid] = tot;
    __syncthreads();
    if (wid == 0 && lane < 8) {
        int w = wsum[lane];
        #pragma unroll
        for (int off = 1; off < 8; off <<= 1) {
            int n = __shfl_up_sync(0xff, w, off);
            if (lane >= off) w += n;
        }
        wsum[lane] = w;
    }
    __syncthreads();

    const int base = (tot - p3) + ((wid > 0) ? wsum[wid - 1] : 0);
    int4 o;
    o.x = base + p0; o.y = base + p1; o.z = base + p2; o.w = base + p3;
    ((int4*)(g_csum + b * SS))[tid] = o;

    // level-1 summary: element 4*tid+3 == 32j+31  <=>  tid % 8 == 7
    if ((tid & 7) == 7) g_sum32[(b << 5) + (tid >> 3)] = o.w;

    if (has_tail && tid == 255) mel_len_out[b] = (float)o.w;
}

// ---------------------------------------------------------------------------
// K2: streaming expand, ONE WARP PER OUTPUT ROW.
// 2-level 32-ary warp search (2 L1-hot 128B loads + 2 ballots), then the
// payload via 256-bit accesses: 2x LDG.256 + 2x STG.256(.cs) per lane
// (1KB contiguous per store wavefront).
// ---------------------------------------------------------------------------
__global__ __launch_bounds__(256)
void lr_expand_kernel(const float* __restrict__ x,
                      float*       __restrict__ out,
                      float*       __restrict__ mask_out,
                      int max_len, int total_rows, int has_tail)
{
    const int row  = (blockIdx.x * blockDim.x + threadIdx.x) >> 5;
    const int lane = threadIdx.x & 31;
    if (row >= total_rows) return;

    const int b = row / max_len;              // warp-uniform
    const int t = row - b * max_len;

    // level 1: 32 segment maxima (one 128B line, L1-hot)
    const int s1  = __ldg(&g_sum32[(b << 5) + lane]);
    const int mel = __shfl_sync(0xffffffff, s1, 31);

    // lane handles floats [lane*8, lane*8+8) and [256+lane*8, 256+lane*8+8)
    float* ob = out + (long)row * DD + lane * 8;

    if (t >= mel) {                           // warp-uniform padding path
        if (has_tail && lane == 0) mask_out[row] = 1.0f;
        float z[8] = {0.f,0.f,0.f,0.f,0.f,0.f,0.f,0.f};
        stg256_cs(ob,       z);
        stg256_cs(ob + 256, z);
        return;
    }
    if (has_tail && lane == 0) mask_out[row] = 0.0f;

    const unsigned m1  = __ballot_sync(0xffffffff, s1 > t);
    const int      seg = __ffs(m1) - 1;

    // level 2: 32 entries of the winning segment (one 128B line)
    const int s2 = __ldg(&g_csum[(b << 10) + (seg << 5) + lane]);
    const unsigned m2 = __ballot_sync(0xffffffff, s2 > t);
    const int lo = (seg << 5) + __ffs(m2) - 1;   // first i with csum[i] > t

    const float* ib = x + ((long)(b * SS + lo)) * DD + lane * 8;
    float v0[8], v1[8];
    ldg256(ib,       v0);
    ldg256(ib + 256, v1);
    stg256_cs(ob,       v0);
    stg256_cs(ob + 256, v1);
}

// ---------------------------------------------------------------------------
extern "C" void kernel_launch(void* const* d_in, const int* in_sizes, int n_in,
                              void* d_out, int out_size)
{
    const float* x   = (const float*)d_in[0];
    const int*   dur = (const int*)d_in[1];
    float*       out = (float*)d_out;

    // Recover max_len from out_size (tuple layout vs expanded-only).
    long L;
    int has_tail;
    long os = (long)out_size;
    if ((os - BB) > 0 && ((os - BB) % ((long)BB * (DD + 1))) == 0) {
        L = (os - BB) / ((long)BB * (DD + 1));
        has_tail = 1;
    } else {
        L = os / ((long)BB * DD);
        has_tail = 0;
    }
    if (L <= 0 || L > MAXL) return;

    const int max_len = (int)L;
    const int total_rows = BB * max_len;

    float* mel_len_out = out + (long)BB * max_len * DD;   // B floats
    float* mask_out    = mel_len_out + BB;                // B*L floats

    // K1: scan only (tiny)
    lr_scan_kernel<<<BB, 256>>>(dur, mel_len_out, has_tail);

    // K2: expand with in-warp 2-level search + 256-bit payload
    {
        const int warps_per_block = 256 / 32;
        const int blocks = (total_rows + warps_per_block - 1) / warps_per_block;
        lr_expand_kernel<<<blocks, 256>>>(x, out, mask_out,
                                          max_len, total_rows, has_tail);
    }
}

// round 11
// speedup vs baseline: 1.0093x; 1.0047x over previous
#include <cuda_runtime.h>

#define BB 32
#define SS 1024
#define DD 512
#define MAXL 8192   // durations in [1,8], S=1024 -> mel_len <= 8192

// 256-bit global load (L1-bypass/nc) and streaming store (sm_100+ PTX v8)
__device__ __forceinline__ void ldg256(const float* p, float* v) {
    asm volatile("ld.global.nc.v8.f32 {%0,%1,%2,%3,%4,%5,%6,%7}, [%8];"
                 : "=f"(v[0]), "=f"(v[1]), "=f"(v[2]), "=f"(v[3]),
                   "=f"(v[4]), "=f"(v[5]), "=f"(v[6]), "=f"(v[7])
                 : "l"(p));
}
__device__ __forceinline__ void stg256_cs(float* p, const float* v) {
    asm volatile("st.global.cs.v8.f32 [%0], {%1,%2,%3,%4,%5,%6,%7,%8};"
                 :: "l"(p),
                    "f"(v[0]), "f"(v[1]), "f"(v[2]), "f"(v[3]),
                    "f"(v[4]), "f"(v[5]), "f"(v[6]), "f"(v[7])
                 : "memory");
}

// ---------------------------------------------------------------------------
// Single kernel, NO inter-block sync. Block (chunk c, batch b) of 8 rows:
//  prologue: re-scan durations[b] (128KB array, L2-resident) into smem
//            (int4 + warp shuffles, 3 barriers, ~hidden under other blocks'
//            in-flight stores)
//  payload:  one warp per row; 2-level 32-ary smem search (LDS + 2 ballots),
//            then 2x LDG.256 + 2x STG.256(.cs) per lane (R10-proven floor).
// ---------------------------------------------------------------------------
__global__ __launch_bounds__(256)
void lr_fused_kernel(const int*   __restrict__ dur,
                     const float* __restrict__ x,
                     float*       __restrict__ out,
                     float*       __restrict__ mel_len_out,
                     float*       __restrict__ mask_out,
                     int max_len, int has_tail)
{
    __shared__ int s[SS];      // inclusive csum of durations[b]
    __shared__ int lvl1[32];   // s[32j+31]
    __shared__ int wsum[8];

    const int b    = blockIdx.y;
    const int tid  = threadIdx.x;
    const int lane = tid & 31;
    const int wid  = tid >> 5;

    // ---- prologue: scan durations[b] into smem ----
    const int4 d = __ldg(((const int4*)(dur + b * SS)) + tid);
    const int p0 = d.x;
    const int p1 = p0 + d.y;
    const int p2 = p1 + d.z;
    const int p3 = p2 + d.w;
    int tot = p3;
    #pragma unroll
    for (int off = 1; off < 32; off <<= 1) {
        int n = __shfl_up_sync(0xffffffff, tot, off);
        if (lane >= off) tot += n;
    }
    if (lane == 31) wsum[wid] = tot;
    __syncthreads();
    if (wid == 0 && lane < 8) {
        int w = wsum[lane];
        #pragma unroll
        for (int off = 1; off < 8; off <<= 1) {
            int n = __shfl_up_sync(0xff, w, off);
            if (lane >= off) w += n;
        }
        wsum[lane] = w;
    }
    __syncthreads();
    const int base = (tot - p3) + ((wid > 0) ? wsum[wid - 1] : 0);
    s[4 * tid + 0] = base + p0;
    s[4 * tid + 1] = base + p1;
    s[4 * tid + 2] = base + p2;
    s[4 * tid + 3] = base + p3;
    if ((tid & 7) == 7) lvl1[tid >> 3] = base + p3;   // element 32j+31
    __syncthreads();

    // ---- payload: one warp per output row ----
    const int t = blockIdx.x * 8 + wid;
    if (t >= max_len) return;
    const int row = b * max_len + t;

    const int s1  = lvl1[lane];                        // LDS, conflict-free
    const int mel = __shfl_sync(0xffffffff, s1, 31);

    if (has_tail) {
        if (blockIdx.x == 0 && tid == 0) mel_len_out[b] = (float)mel;
        if (lane == 0) mask_out[row] = (t >= mel) ? 1.0f : 0.0f;
    }

    float* ob = out + (long)row * DD + lane * 8;

    if (t >= mel) {                                    // warp-uniform padding
        float z[8] = {0.f,0.f,0.f,0.f,0.f,0.f,0.f,0.f};
        stg256_cs(ob,       z);
        stg256_cs(ob + 256, z);
        return;
    }

    const unsigned m1  = __ballot_sync(0xffffffff, s1 > t);
    const int      seg = __ffs(m1) - 1;
    const int s2 = s[(seg << 5) + lane];
    const unsigned m2 = __ballot_sync(0xffffffff, s2 > t);
    const int lo = (seg << 5) + __ffs(m2) - 1;         // first i with csum[i] > t

    const float* ib = x + ((long)(b * SS + lo)) * DD + lane * 8;
    float v0[8], v1[8];
    ldg256(ib,       v0);
    ldg256(ib + 256, v1);
    stg256_cs(ob,       v0);
    stg256_cs(ob + 256, v1);
}

// ---------------------------------------------------------------------------
extern "C" void kernel_launch(void* const* d_in, const int* in_sizes, int n_in,
                              void* d_out, int out_size)
{
    const float* x   = (const float*)d_in[0];
    const int*   dur = (const int*)d_in[1];
    float*       out = (float*)d_out;

    // Recover max_len from out_size (tuple layout vs expanded-only).
    long L;
    int has_tail;
    long os = (long)out_size;
    if ((os - BB) > 0 && ((os - BB) % ((long)BB * (DD + 1))) == 0) {
        L = (os - BB) / ((long)BB * (DD + 1));
        has_tail = 1;
    } else {
        L = os / ((long)BB * DD);
        has_tail = 0;
    }
    if (L <= 0 || L > MAXL) return;

    const int max_len = (int)L;
    const int bpb = (max_len + 7) / 8;    // blocks per batch (8 rows/block)

    float* mel_len_out = out + (long)BB * max_len * DD;   // B floats
    float* mask_out    = mel_len_out + BB;                // B*L floats

    dim3 grid((unsigned)bpb, BB, 1);
    lr_fused_kernel<<<grid, 256>>>(dur, x, out, mel_len_out, mask_out,
                                   max_len, has_tail);
}